// round 14
// baseline (speedup 1.0000x reference)
#include <cuda_runtime.h>
#include <cuda_fp16.h>
#include <math_constants.h>
#include <math.h>
#include <stdint.h>

#define B_   4
#define S_   2048
#define H_   12
#define DM_  768
#define MROWS (B_*S_)   // 8192

// ---------------- scratch ----------------
__device__ __half g_Cq [MROWS*128];
__device__ __half g_Ckv[MROWS*128];
__device__ __half g_q  [(size_t)B_*H_*S_*128];
__device__ __half g_k  [(size_t)B_*H_*S_*128];
__device__ __half g_vh [(size_t)B_*H_*S_*128];
__device__ __half g_o  [MROWS*1536];
__device__ __half g_xh [MROWS*768];
__device__ __half g_Wh [2457600];
__device__ float  g_p0 [MROWS*768];
__device__ float  g_p1 [MROWS*768];
__device__ float  g_freq[384];

#define WR_UQN 0
#define WR_UQR 98304
#define WR_UKN 196608
#define WR_UV  294912
#define WR_UKR 491520
#define WR_O   1081344
#define WR_DQ  2260992
#define WR_DKV 2359296

// ---------------- helpers ----------------
__device__ __forceinline__ void mma16(float* d, const uint32_t* a, const uint32_t* b) {
    asm volatile(
        "mma.sync.aligned.m16n8k16.row.col.f32.f16.f16.f32 "
        "{%0,%1,%2,%3},{%4,%5,%6,%7},{%8,%9},{%0,%1,%2,%3};"
        : "+f"(d[0]), "+f"(d[1]), "+f"(d[2]), "+f"(d[3])
        : "r"(a[0]), "r"(a[1]), "r"(a[2]), "r"(a[3]), "r"(b[0]), "r"(b[1]));
}
__device__ __forceinline__ uint32_t smem_u32(const void* p) {
    return (uint32_t)__cvta_generic_to_shared(p);
}
__device__ __forceinline__ void cpasync16(uint32_t dst, const void* src) {
    asm volatile("cp.async.cg.shared.global [%0], [%1], 16;" :: "r"(dst), "l"(src));
}
__device__ __forceinline__ uint32_t packh2(float a, float b) {
    __half2 h = __floats2half2_rn(a, b);
    return *(uint32_t*)&h;
}
__device__ __forceinline__ void ldsm_x4(uint32_t* r, uint32_t addr) {
    asm volatile("ldmatrix.sync.aligned.m8n8.x4.shared.b16 {%0,%1,%2,%3}, [%4];"
        : "=r"(r[0]), "=r"(r[1]), "=r"(r[2]), "=r"(r[3]) : "r"(addr));
}
__device__ __forceinline__ void ldsm_x4t(uint32_t* r, uint32_t addr) {
    asm volatile("ldmatrix.sync.aligned.m8n8.x4.trans.shared.b16 {%0,%1,%2,%3}, [%4];"
        : "=r"(r[0]), "=r"(r[1]), "=r"(r[2]), "=r"(r[3]) : "r"(addr));
}

// ---------------- freq table ----------------
__global__ void init_freq_kernel() {
    int i = threadIdx.x + blockIdx.x * blockDim.x;
    if (i < 384)
        g_freq[i] = (float)exp(-((double)(2 * i) / 768.0) * log(10000.0));
}

// ---------------- convert fp32 -> fp16 ----------------
struct CTasks {
    const float* src[9];
    __half* dst[9];
    int end4[9];
};
__global__ void conv_half_kernel(CTasks ct) {
    int idx = blockIdx.x * blockDim.x + threadIdx.x;
    if (idx >= ct.end4[8]) return;
    int ti = 0;
    while (idx >= ct.end4[ti]) ti++;
    int off = ti ? idx - ct.end4[ti - 1] : idx;
    float4 v = ((const float4*)ct.src[ti])[off];
    __half2* d = (__half2*)ct.dst[ti];
    d[off * 2]     = __floats2half2_rn(v.x, v.y);
    d[off * 2 + 1] = __floats2half2_rn(v.z, v.w);
}

// ---------------- split-K reduction: out = p0 + p1 + bias ----------------
__global__ void addbias_kernel(const float* __restrict__ p0, const float* __restrict__ p1,
                               const float* __restrict__ bias, float* __restrict__ out, int n4) {
    int i = blockIdx.x * blockDim.x + threadIdx.x;
    if (i >= n4) return;
    float4 a = ((const float4*)p0)[i];
    float4 b = ((const float4*)p1)[i];
    float4 bv = ((const float4*)bias)[i % 192];   // 768 floats = 192 float4
    float4 r;
    r.x = a.x + b.x + bv.x;
    r.y = a.y + b.y + bv.y;
    r.z = a.z + b.z + bv.z;
    r.w = a.w + b.w + bv.w;
    ((float4*)out)[i] = r;
}

// ---------------- shared task structs ----------------
// modes: 0 plain fp32+bias  1 q_nope  2 q_rope  3 k_nope  4 k_rope  5 v_scatter
//        6 plain half+bias  7 raw fp32 partial (no bias)
struct GTask {
    const void* X; const void* W; const float* bias; void* Y;
    int K, mode, ntx, base, ldx, ldw;
};
struct GTasks { GTask t[6]; int n; int nblocks; };

// =============== WIDE GEMM: 128x128 tiles, TBK=64, 3-stage, 2 CTAs/SM ===============
#define GST_W 36
#define STG_W 4608
#define MG_SMEM_W (3 * 2 * STG_W * 4)    // 110592 B

__global__ __launch_bounds__(256, 2)
void gemm_wide(GTasks tasks)
{
    extern __shared__ uint32_t sm4[];
    const uint32_t sb = smem_u32(sm4);

    int bid = blockIdx.x;
    if (bid >= tasks.nblocks) return;
    int ti = 0;
#pragma unroll 1
    while (ti + 1 < tasks.n && bid >= tasks.t[ti + 1].base) ti++;
    const GTask tk = tasks.t[ti];
    int lb = bid - tk.base;
    int tilex = lb % tk.ntx;
    int tiley = lb / tk.ntx;

    const int tid  = threadIdx.x;
    const int lane = tid & 31;
    const int wid  = tid >> 5;
    const int g    = lane >> 2;
    const int t    = lane & 3;
    const int wm   = wid & 3;
    const int wn   = wid >> 2;
    const int K    = tk.K;
    const int ldx  = tk.ldx;
    const int ldw  = tk.ldw;
    const int kiters = K >> 6;

    const int lm = lane >> 3, lr = lane & 7;
    const int constA = ((lm & 1) * 8 + lr) * GST_W + (lm >> 1) * 4;
    const int constB = ((lm >> 1) * 8 + lr) * GST_W + (lm & 1) * 4;

    const __half* Xb = (const __half*)tk.X + (size_t)(tiley * 128) * ldx;
    const __half* Wb = (const __half*)tk.W + (size_t)(tilex * 128) * ldw;

    float acc[2][8][4];
#pragma unroll
    for (int mt = 0; mt < 2; mt++)
#pragma unroll
        for (int nt = 0; nt < 8; nt++)
#pragma unroll
            for (int j = 0; j < 4; j++) acc[mt][nt][j] = 0.f;

#pragma unroll
    for (int st = 0; st < 2; st++) {
        uint32_t As = sb + st * (2 * STG_W) * 4;
        uint32_t Bs = As + STG_W * 4;
        int k0 = st * 64;
#pragma unroll
        for (int i = 0; i < 8; i++) {
            int ch = tid + (i & 3) * 256;
            int r = ch >> 3, c = ch & 7;
            if (i < 4) cpasync16(As + (r * GST_W + c * 4) * 4, Xb + (size_t)r * ldx + k0 + c * 8);
            else       cpasync16(Bs + (r * GST_W + c * 4) * 4, Wb + (size_t)r * ldw + k0 + c * 8);
        }
        asm volatile("cp.async.commit_group;");
    }

    for (int ki = 0; ki < kiters; ki++) {
        if (ki + 1 < kiters) asm volatile("cp.async.wait_group 1;");
        else                 asm volatile("cp.async.wait_group 0;");
        __syncthreads();

        if (ki + 2 < kiters) {
            int st = (ki + 2) % 3;
            uint32_t As = sb + st * (2 * STG_W) * 4;
            uint32_t Bs = As + STG_W * 4;
            int k0 = (ki + 2) * 64;
#pragma unroll
            for (int i = 0; i < 8; i++) {
                int ch = tid + (i & 3) * 256;
                int r = ch >> 3, c = ch & 7;
                if (i < 4) cpasync16(As + (r * GST_W + c * 4) * 4, Xb + (size_t)r * ldx + k0 + c * 8);
                else       cpasync16(Bs + (r * GST_W + c * 4) * 4, Wb + (size_t)r * ldw + k0 + c * 8);
            }
            asm volatile("cp.async.commit_group;");
        }

        const uint32_t As = sb + (ki % 3) * (2 * STG_W) * 4;
        const uint32_t Bs = As + STG_W * 4;

#pragma unroll
        for (int kk = 0; kk < 4; kk++) {
            uint32_t af[2][4];
            ldsm_x4(af[0], As + (constA + (wm * 32)      * GST_W + kk * 8) * 4);
            ldsm_x4(af[1], As + (constA + (wm * 32 + 16) * GST_W + kk * 8) * 4);
#pragma unroll
            for (int ntp = 0; ntp < 4; ntp++) {
                uint32_t bf[4];
                ldsm_x4(bf, Bs + (constB + (wn * 64 + ntp * 16) * GST_W + kk * 8) * 4);
                mma16(acc[0][2 * ntp],     af[0], bf);
                mma16(acc[0][2 * ntp + 1], af[0], bf + 2);
                mma16(acc[1][2 * ntp],     af[1], bf);
                mma16(acc[1][2 * ntp + 1], af[1], bf + 2);
            }
        }
    }

    const int N = tk.ntx << 7;
    const int mode = tk.mode;

#pragma unroll
    for (int mt = 0; mt < 2; mt++) {
        int r0 = tiley * 128 + wm * 32 + mt * 16 + g;
#pragma unroll
        for (int nt = 0; nt < 8; nt++) {
            int n = tilex * 128 + wn * 64 + nt * 8 + 2 * t;
            float b0 = 0.f, b1 = 0.f;
            if (mode != 7) { b0 = tk.bias[n]; b1 = tk.bias[n + 1]; }
            float x0 = acc[mt][nt][0] + b0, y0 = acc[mt][nt][1] + b1;
            float x1 = acc[mt][nt][2] + b0, y1 = acc[mt][nt][3] + b1;

            if (mode == 6) {
                __half* Yh = (__half*)tk.Y;
                *(__half2*)&Yh[(size_t)r0 * N + n]       = __floats2half2_rn(x0, y0);
                *(__half2*)&Yh[(size_t)(r0 + 8) * N + n] = __floats2half2_rn(x1, y1);
            } else {   // mode 0 or 7: fp32 store
                float* Yf = (float*)tk.Y;
                *(float2*)&Yf[(size_t)r0 * N + n]       = make_float2(x0, y0);
                *(float2*)&Yf[(size_t)(r0 + 8) * N + n] = make_float2(x1, y1);
            }
        }
    }
}

// =============== NARROW GEMM: 128x64 tiles, TBK=32, 4-stage, 3 CTAs/SM ===============
#define GST_N 20
#define STG_NA 2560
#define STG_NB 1280
#define STG_N (STG_NA + STG_NB)          // 3840
#define NSTAGE_N 4
#define MG_SMEM_N (NSTAGE_N * STG_N * 4) // 61440 B

__global__ __launch_bounds__(256, 3)
void gemm_narrow(GTasks tasks)
{
    extern __shared__ uint32_t sm4[];
    const uint32_t sb = smem_u32(sm4);

    int bid = blockIdx.x;
    if (bid >= tasks.nblocks) return;
    int ti = 0;
#pragma unroll 1
    while (ti + 1 < tasks.n && bid >= tasks.t[ti + 1].base) ti++;
    const GTask tk = tasks.t[ti];
    int lb = bid - tk.base;
    int tilex = lb % tk.ntx;
    int tiley = lb / tk.ntx;

    const int tid  = threadIdx.x;
    const int lane = tid & 31;
    const int wid  = tid >> 5;
    const int g    = lane >> 2;
    const int t    = lane & 3;
    const int wm   = wid & 3;
    const int wn   = wid >> 2;
    const int K    = tk.K;
    const int ldx  = tk.ldx;
    const int ldw  = tk.ldw;

    const int lm = lane >> 3, lr = lane & 7;
    const int constA = ((lm & 1) * 8 + lr) * GST_N + (lm >> 1) * 4;
    const int constB = ((lm >> 1) * 8 + lr) * GST_N + (lm & 1) * 4;

    const __half* Xb = (const __half*)tk.X + (size_t)(tiley * 128) * ldx;
    const __half* Wb = (const __half*)tk.W + (size_t)(tilex * 64) * ldw;

    float acc[2][4][4];
#pragma unroll
    for (int mt = 0; mt < 2; mt++)
#pragma unroll
        for (int nt = 0; nt < 4; nt++)
#pragma unroll
            for (int j = 0; j < 4; j++) acc[mt][nt][j] = 0.f;

    auto load_chunk = [&](int j) {
        uint32_t Sb = sb + (j % NSTAGE_N) * STG_N * 4;
#pragma unroll
        for (int i = 0; i < 3; i++) {
            int ch = tid + i * 256;
            if (ch < 512) {
                int r = ch >> 2, c = ch & 3;
                cpasync16(Sb + (r * GST_N + c * 4) * 4, Xb + (size_t)r * ldx + j * 32 + c * 8);
            } else {
                int ch2 = ch - 512;
                int r = ch2 >> 2, c = ch2 & 3;
                cpasync16(Sb + (STG_NA + r * GST_N + c * 4) * 4, Wb + (size_t)r * ldw + j * 32 + c * 8);
            }
        }
    };

    auto compute_stage = [&](int st) {
        const uint32_t As = sb + st * STG_N * 4;
        const uint32_t Bs = As + STG_NA * 4;
#pragma unroll
        for (int kk = 0; kk < 2; kk++) {
            uint32_t af[2][4];
            ldsm_x4(af[0], As + (constA + (wm * 32)      * GST_N + kk * 8) * 4);
            ldsm_x4(af[1], As + (constA + (wm * 32 + 16) * GST_N + kk * 8) * 4);
#pragma unroll
            for (int ntp = 0; ntp < 2; ntp++) {
                uint32_t bf[4];
                ldsm_x4(bf, Bs + (constB + (wn * 32 + ntp * 16) * GST_N + kk * 8) * 4);
                mma16(acc[0][2 * ntp],     af[0], bf);
                mma16(acc[0][2 * ntp + 1], af[0], bf + 2);
                mma16(acc[1][2 * ntp],     af[1], bf);
                mma16(acc[1][2 * ntp + 1], af[1], bf + 2);
            }
        }
    };

    if (K == 128) {
        // fast path: all 4 chunks fit in the 4 stages; single wait + barrier
#pragma unroll
        for (int j = 0; j < 4; j++) load_chunk(j);
        asm volatile("cp.async.commit_group;");
        asm volatile("cp.async.wait_group 0;");
        __syncthreads();
#pragma unroll
        for (int ki = 0; ki < 4; ki++) compute_stage(ki);
    } else {
        const int kiters = K >> 5;
#pragma unroll
        for (int j = 0; j < NSTAGE_N - 1; j++) {
            load_chunk(j);
            asm volatile("cp.async.commit_group;");
        }
        for (int ki = 0; ki < kiters; ki++) {
            asm volatile("cp.async.wait_group 2;");
            __syncthreads();
            if (ki + NSTAGE_N - 1 < kiters) load_chunk(ki + NSTAGE_N - 1);
            asm volatile("cp.async.commit_group;");
            compute_stage(ki % NSTAGE_N);
        }
    }

    const float scale = 0.08838834764831845f;   // 1/sqrt(128)
    const int mode = tk.mode;

#pragma unroll
    for (int mt = 0; mt < 2; mt++) {
        int r0 = tiley * 128 + wm * 32 + mt * 16 + g;
#pragma unroll
        for (int nt = 0; nt < 4; nt++) {
            int n = tilex * 64 + wn * 32 + nt * 8 + 2 * t;
            float b0 = tk.bias[n], b1 = tk.bias[n + 1];
            float x0 = acc[mt][nt][0] + b0, y0 = acc[mt][nt][1] + b1;
            float x1 = acc[mt][nt][2] + b0, y1 = acc[mt][nt][3] + b1;

            int s0 = r0 & 2047;
            int f = n;
            if (mode == 2 || mode == 4) {   // rope
                f = 768 + n;
                float fr = g_freq[n >> 1];
                float a0 = (float)s0 * fr;
                float a1 = (float)(s0 + 8) * fr;
                float c0 = cosf(a0), sn0 = sinf(a0);
                float c1 = cosf(a1), sn1 = sinf(a1);
                float tx0 = x0 * c0 - y0 * sn0, ty0 = x0 * sn0 + y0 * c0;
                float tx1 = x1 * c1 - y1 * sn1, ty1 = x1 * sn1 + y1 * c1;
                x0 = tx0; y0 = ty0; x1 = tx1; y1 = ty1;
            }
            if (mode <= 2) { x0 *= scale; y0 *= scale; x1 *= scale; y1 *= scale; }
            int h = f >> 7, d = f & 127;
            int b = r0 >> 11;
            __half* Yh = (__half*)tk.Y;
            size_t d0 = (((size_t)(b * H_ + h)) * S_ + s0) * 128 + d;
            *(__half2*)&Yh[d0]           = __floats2half2_rn(x0, y0);
            *(__half2*)&Yh[d0 + 8 * 128] = __floats2half2_rn(x1, y1);
        }
    }
}

// ---------------- FP16 flash attention (R13, unchanged) ----------------
#define AKST 68
#define OFF_K0  0
#define OFF_K1  4352
#define OFF_VN0 8704
#define OFF_VN1 13056
#define ATT_SMEM_BYTES (17408 * 4)   // 69632

__global__ __launch_bounds__(256, 1)
void attn_f16(const __half* __restrict__ q, const __half* __restrict__ k,
              const __half* __restrict__ v, __half* __restrict__ o)
{
    extern __shared__ uint32_t sm4[];
    const uint32_t sb = smem_u32(sm4);

    const int tid  = threadIdx.x;
    const int lane = tid & 31;
    const int wid  = tid >> 5;
    const int g    = lane >> 2;
    const int t    = lane & 3;
    const int qt   = (S_ / 128 - 1) - blockIdx.x;
    const int bh   = blockIdx.y;
    const int b    = bh / H_, h = bh % H_;
    const size_t base = (size_t)bh * S_ * 128;

    const int lm = lane >> 3, lr = lane & 7;
    const int constA = ((lm & 1) * 8 + lr) * AKST + (lm >> 1) * 4;
    const int constB = ((lm >> 1) * 8 + lr) * AKST + (lm & 1) * 4;

    {
        const __half* qg = q + base + (size_t)qt * 128 * 128;
#pragma unroll
        for (int i = 0; i < 8; i++) {
            int ch = tid + i * 256;
            int r = ch >> 4, c4 = (ch & 15) << 2;
            cpasync16(sb + (r * AKST + c4) * 4, qg + (size_t)r * 128 + ((ch & 15) << 3));
        }
        asm volatile("cp.async.commit_group;");
        asm volatile("cp.async.wait_group 0;");
        __syncthreads();
    }

    const int wr = wid * 16;
    uint32_t qf[8][4];
#pragma unroll
    for (int kk = 0; kk < 8; kk++)
        ldsm_x4(qf[kk], sb + (constA + wr * AKST + kk * 8) * 4);
    __syncthreads();

    float of[16][4];
#pragma unroll
    for (int nt = 0; nt < 16; nt++)
#pragma unroll
        for (int j = 0; j < 4; j++) of[nt][j] = 0.f;
    float m0 = -CUDART_INF_F, m1 = -CUDART_INF_F, l0 = 0.f, l1 = 0.f;

    const int row0g = qt * 128 + wr + g;
    const int row1g = row0g + 8;
    const int nkt = 2 * qt + 2;

    {
        const __half* kg = k + base;
        const __half* vg = v + base;
#pragma unroll
        for (int i = 0; i < 8; i++) {
            int ch = tid + (i & 3) * 256;
            int r = ch >> 4, c4 = (ch & 15) << 2, c8 = (ch & 15) << 3;
            if (i < 4) cpasync16(sb + (OFF_K0  + r * AKST + c4) * 4, kg + (size_t)r * 128 + c8);
            else       cpasync16(sb + (OFF_VN0 + r * AKST + c4) * 4, vg + (size_t)r * 128 + c8);
        }
        asm volatile("cp.async.commit_group;");
    }

    for (int kt = 0; kt < nkt; kt++) {
        asm volatile("cp.async.wait_group 0;");
        __syncthreads();

        if (kt + 1 < nkt) {
            const __half* kg = k + base + (size_t)(kt + 1) * 64 * 128;
            const __half* vg = v + base + (size_t)(kt + 1) * 64 * 128;
            uint32_t Kd = sb + ((((kt + 1) & 1) ? OFF_K1  : OFF_K0))  * 4;
            uint32_t Vd = sb + ((((kt + 1) & 1) ? OFF_VN1 : OFF_VN0)) * 4;
#pragma unroll
            for (int i = 0; i < 8; i++) {
                int ch = tid + (i & 3) * 256;
                int r = ch >> 4, c4 = (ch & 15) << 2, c8 = (ch & 15) << 3;
                if (i < 4) cpasync16(Kd + (r * AKST + c4) * 4, kg + (size_t)r * 128 + c8);
                else       cpasync16(Vd + (r * AKST + c4) * 4, vg + (size_t)r * 128 + c8);
            }
            asm volatile("cp.async.commit_group;");
        }

        const uint32_t Kb = sb + (((kt & 1) ? OFF_K1  : OFF_K0))  * 4;
        const uint32_t Vn = sb + (((kt & 1) ? OFF_VN1 : OFF_VN0)) * 4;

        float sc[8][4];
#pragma unroll
        for (int nt = 0; nt < 8; nt++)
#pragma unroll
            for (int j = 0; j < 4; j++) sc[nt][j] = 0.f;

#pragma unroll
        for (int kk = 0; kk < 8; kk++) {
#pragma unroll
            for (int ntp = 0; ntp < 4; ntp++) {
                uint32_t bf[4];
                ldsm_x4(bf, Kb + (constB + ntp * 16 * AKST + kk * 8) * 4);
                mma16(sc[2 * ntp],     qf[kk], bf);
                mma16(sc[2 * ntp + 1], qf[kk], bf + 2);
            }
        }

        if (kt >= 2 * qt) {
            int cbase = kt * 64 + 2 * t;
#pragma unroll
            for (int nt = 0; nt < 8; nt++) {
                int col = cbase + nt * 8;
                if (col     > row0g) sc[nt][0] = -CUDART_INF_F;
                if (col + 1 > row0g) sc[nt][1] = -CUDART_INF_F;
                if (col     > row1g) sc[nt][2] = -CUDART_INF_F;
                if (col + 1 > row1g) sc[nt][3] = -CUDART_INF_F;
            }
        }

        float rmax0 = -CUDART_INF_F, rmax1 = -CUDART_INF_F;
#pragma unroll
        for (int nt = 0; nt < 8; nt++) {
            rmax0 = fmaxf(rmax0, fmaxf(sc[nt][0], sc[nt][1]));
            rmax1 = fmaxf(rmax1, fmaxf(sc[nt][2], sc[nt][3]));
        }
        rmax0 = fmaxf(rmax0, __shfl_xor_sync(0xffffffffu, rmax0, 1, 4));
        rmax0 = fmaxf(rmax0, __shfl_xor_sync(0xffffffffu, rmax0, 2, 4));
        rmax1 = fmaxf(rmax1, __shfl_xor_sync(0xffffffffu, rmax1, 1, 4));
        rmax1 = fmaxf(rmax1, __shfl_xor_sync(0xffffffffu, rmax1, 2, 4));

        float mn0 = fmaxf(m0, rmax0);
        float mn1 = fmaxf(m1, rmax1);
        float fac0 = __expf(m0 - mn0);
        float fac1 = __expf(m1 - mn1);
        m0 = mn0; m1 = mn1;

        float rs0 = 0.f, rs1 = 0.f;
#pragma unroll
        for (int nt = 0; nt < 8; nt++) {
            float p0 = __expf(sc[nt][0] - mn0);
            float p1 = __expf(sc[nt][1] - mn0);
            float p2 = __expf(sc[nt][2] - mn1);
            float p3 = __expf(sc[nt][3] - mn1);
            sc[nt][0] = p0; sc[nt][1] = p1; sc[nt][2] = p2; sc[nt][3] = p3;
            rs0 += p0 + p1; rs1 += p2 + p3;
        }
        rs0 += __shfl_xor_sync(0xffffffffu, rs0, 1, 4);
        rs0 += __shfl_xor_sync(0xffffffffu, rs0, 2, 4);
        rs1 += __shfl_xor_sync(0xffffffffu, rs1, 1, 4);
        rs1 += __shfl_xor_sync(0xffffffffu, rs1, 2, 4);
        l0 = l0 * fac0 + rs0;
        l1 = l1 * fac1 + rs1;

#pragma unroll
        for (int nt = 0; nt < 16; nt++) {
            of[nt][0] *= fac0; of[nt][1] *= fac0;
            of[nt][2] *= fac1; of[nt][3] *= fac1;
        }

#pragma unroll
        for (int kk = 0; kk < 4; kk++) {
            uint32_t ap[4];
            ap[0] = packh2(sc[2 * kk][0],     sc[2 * kk][1]);
            ap[1] = packh2(sc[2 * kk][2],     sc[2 * kk][3]);
            ap[2] = packh2(sc[2 * kk + 1][0], sc[2 * kk + 1][1]);
            ap[3] = packh2(sc[2 * kk + 1][2], sc[2 * kk + 1][3]);
#pragma unroll
            for (int ntp = 0; ntp < 8; ntp++) {
                uint32_t bf[4];
                ldsm_x4t(bf, Vn + (constA + kk * 16 * AKST + ntp * 8) * 4);
                mma16(of[2 * ntp],     ap, bf);
                mma16(of[2 * ntp + 1], ap, bf + 2);
            }
        }
    }

    float inv0 = 1.0f / l0;
    float inv1 = 1.0f / l1;
    size_t orow0 = ((size_t)(b * S_ + row0g)) * 1536 + h * 128;
    size_t orow1 = ((size_t)(b * S_ + row1g)) * 1536 + h * 128;
#pragma unroll
    for (int nt = 0; nt < 16; nt++) {
        int col = nt * 8 + 2 * t;
        *(__half2*)&o[orow0 + col] = __floats2half2_rn(of[nt][0] * inv0, of[nt][1] * inv0);
        *(__half2*)&o[orow1 + col] = __floats2half2_rn(of[nt][2] * inv1, of[nt][3] * inv1);
    }
}

// ---------------- launch ----------------
extern "C" void kernel_launch(void* const* d_in, const int* in_sizes, int n_in,
                              void* d_out, int out_size)
{
    const float* x         = (const float*)d_in[0];
    const float* W_dkv     = (const float*)d_in[2];
    const float* b_dkv     = (const float*)d_in[3];
    const float* W_dq      = (const float*)d_in[4];
    const float* b_dq      = (const float*)d_in[5];
    const float* W_uk_nope = (const float*)d_in[6];
    const float* b_uk_nope = (const float*)d_in[7];
    const float* W_uv      = (const float*)d_in[8];
    const float* b_uv      = (const float*)d_in[9];
    const float* W_uq_nope = (const float*)d_in[10];
    const float* b_uq_nope = (const float*)d_in[11];
    const float* W_uq_rope = (const float*)d_in[12];
    const float* b_uq_rope = (const float*)d_in[13];
    const float* W_uk_rope = (const float*)d_in[14];
    const float* b_uk_rope = (const float*)d_in[15];
    const float* W_o       = (const float*)d_in[16];
    const float* b_o       = (const float*)d_in[17];
    float* out = (float*)d_out;

    __half *Cq, *Ckv, *q, *k, *vh, *o, *xh, *Wh;
    float *p0, *p1;
    cudaGetSymbolAddress((void**)&Cq,  g_Cq);
    cudaGetSymbolAddress((void**)&Ckv, g_Ckv);
    cudaGetSymbolAddress((void**)&q,   g_q);
    cudaGetSymbolAddress((void**)&k,   g_k);
    cudaGetSymbolAddress((void**)&vh,  g_vh);
    cudaGetSymbolAddress((void**)&o,   g_o);
    cudaGetSymbolAddress((void**)&xh,  g_xh);
    cudaGetSymbolAddress((void**)&Wh,  g_Wh);
    cudaGetSymbolAddress((void**)&p0,  g_p0);
    cudaGetSymbolAddress((void**)&p1,  g_p1);

    cudaFuncSetAttribute(attn_f16, cudaFuncAttributeMaxDynamicSharedMemorySize, ATT_SMEM_BYTES);
    cudaFuncSetAttribute(gemm_wide, cudaFuncAttributeMaxDynamicSharedMemorySize, MG_SMEM_W);
    cudaFuncSetAttribute(gemm_narrow, cudaFuncAttributeMaxDynamicSharedMemorySize, MG_SMEM_N);

    dim3 t(256);
    init_freq_kernel<<<2, 192>>>();

    // convert x and all fp16-consumed weights
    CTasks ct;
    ct.src[0] = x;         ct.dst[0] = xh;
    ct.src[1] = W_uq_nope; ct.dst[1] = Wh + WR_UQN;
    ct.src[2] = W_uq_rope; ct.dst[2] = Wh + WR_UQR;
    ct.src[3] = W_uk_nope; ct.dst[3] = Wh + WR_UKN;
    ct.src[4] = W_uv;      ct.dst[4] = Wh + WR_UV;
    ct.src[5] = W_uk_rope; ct.dst[5] = Wh + WR_UKR;
    ct.src[6] = W_o;       ct.dst[6] = Wh + WR_O;
    ct.src[7] = W_dq;      ct.dst[7] = Wh + WR_DQ;
    ct.src[8] = W_dkv;     ct.dst[8] = Wh + WR_DKV;
    int counts[9] = {MROWS*768, 98304, 98304, 98304, 196608, 589824, 1179648, 98304, 98304};
    int acc4 = 0;
    for (int i = 0; i < 9; i++) { acc4 += counts[i] / 4; ct.end4[i] = acc4; }
    conv_half_kernel<<<(acc4 + 255) / 256, 256>>>(ct);

    // latent projections (wide GEMM, half outputs)
    GTasks gl;
    gl.n = 2;
    gl.nblocks = 128;
    gl.t[0] = { xh, Wh + WR_DQ,  b_dq,  Cq,  768, 6, 1, 0,  768, 768 };
    gl.t[1] = { xh, Wh + WR_DKV, b_dkv, Ckv, 768, 6, 1, 64, 768, 768 };
    gemm_wide<<<128, t, MG_SMEM_W>>>(gl);

    // five up-projections fused (narrow GEMM, heavy-K k_rope first)
    GTasks gt;
    gt.n = 5;
    gt.nblocks = 4608;
    gt.t[0] = { xh,  Wh + WR_UKR, b_uk_rope, k,   768, 4, 12, 0,    768, 768 };
    gt.t[1] = { Ckv, Wh + WR_UV,  b_uv,      vh,  128, 5, 24, 768,  128, 128 };
    gt.t[2] = { Cq,  Wh + WR_UQN, b_uq_nope, q,   128, 1, 12, 2304, 128, 128 };
    gt.t[3] = { Cq,  Wh + WR_UQR, b_uq_rope, q,   128, 2, 12, 3072, 128, 128 };
    gt.t[4] = { Ckv, Wh + WR_UKN, b_uk_nope, k,   128, 3, 12, 3840, 128, 128 };
    gemm_narrow<<<4608, t, MG_SMEM_N>>>(gt);

    // fp16 flash attention
    attn_f16<<<dim3(S_ / 128, B_ * H_), t, ATT_SMEM_BYTES>>>(q, k, vh, o);

    // output projection: split-K into two half-tasks in one launch, then reduce
    GTasks go;
    go.n = 2;
    go.nblocks = 768;
    go.t[0] = { o,       Wh + WR_O,       b_o, p0, 768, 7, 6, 0,   1536, 1536 };
    go.t[1] = { o + 768, Wh + WR_O + 768, b_o, p1, 768, 7, 6, 384, 1536, 1536 };
    gemm_wide<<<768, t, MG_SMEM_W>>>(go);
    addbias_kernel<<<(MROWS * 768 / 4 + 255) / 256, 256>>>(p0, p1, b_o, out, MROWS * 768 / 4);
}

// round 15
// speedup vs baseline: 1.0191x; 1.0191x over previous
#include <cuda_runtime.h>
#include <cuda_fp16.h>
#include <math_constants.h>
#include <math.h>
#include <stdint.h>

#define B_   4
#define S_   2048
#define H_   12
#define DM_  768
#define MROWS (B_*S_)   // 8192

// ---------------- scratch ----------------
__device__ __half g_Cq [MROWS*128];
__device__ __half g_Ckv[MROWS*128];
__device__ __half g_q  [(size_t)B_*H_*S_*128];
__device__ __half g_k  [(size_t)B_*H_*S_*128];
__device__ __half g_vh [(size_t)B_*H_*S_*128];
__device__ __half g_o  [MROWS*1536];
__device__ __half g_xh [MROWS*768];
__device__ __half g_Wh [2457600];
__device__ float  g_freq[384];

#define WR_UQN 0
#define WR_UQR 98304
#define WR_UKN 196608
#define WR_UV  294912
#define WR_UKR 491520
#define WR_O   1081344
#define WR_DQ  2260992
#define WR_DKV 2359296

// ---------------- helpers ----------------
__device__ __forceinline__ void mma16(float* d, const uint32_t* a, const uint32_t* b) {
    asm volatile(
        "mma.sync.aligned.m16n8k16.row.col.f32.f16.f16.f32 "
        "{%0,%1,%2,%3},{%4,%5,%6,%7},{%8,%9},{%0,%1,%2,%3};"
        : "+f"(d[0]), "+f"(d[1]), "+f"(d[2]), "+f"(d[3])
        : "r"(a[0]), "r"(a[1]), "r"(a[2]), "r"(a[3]), "r"(b[0]), "r"(b[1]));
}
__device__ __forceinline__ uint32_t smem_u32(const void* p) {
    return (uint32_t)__cvta_generic_to_shared(p);
}
__device__ __forceinline__ void cpasync16(uint32_t dst, const void* src) {
    asm volatile("cp.async.cg.shared.global [%0], [%1], 16;" :: "r"(dst), "l"(src));
}
__device__ __forceinline__ uint32_t packh2(float a, float b) {
    __half2 h = __floats2half2_rn(a, b);
    return *(uint32_t*)&h;
}
__device__ __forceinline__ void ldsm_x4(uint32_t* r, uint32_t addr) {
    asm volatile("ldmatrix.sync.aligned.m8n8.x4.shared.b16 {%0,%1,%2,%3}, [%4];"
        : "=r"(r[0]), "=r"(r[1]), "=r"(r[2]), "=r"(r[3]) : "r"(addr));
}
__device__ __forceinline__ void ldsm_x4t(uint32_t* r, uint32_t addr) {
    asm volatile("ldmatrix.sync.aligned.m8n8.x4.trans.shared.b16 {%0,%1,%2,%3}, [%4];"
        : "=r"(r[0]), "=r"(r[1]), "=r"(r[2]), "=r"(r[3]) : "r"(addr));
}

// ---------------- freq table ----------------
__global__ void init_freq_kernel() {
    int i = threadIdx.x + blockIdx.x * blockDim.x;
    if (i < 384)
        g_freq[i] = (float)exp(-((double)(2 * i) / 768.0) * log(10000.0));
}

// ---------------- convert fp32 -> fp16 ----------------
struct CTasks {
    const float* src[9];
    __half* dst[9];
    int end4[9];
};
__global__ void conv_half_kernel(CTasks ct) {
    int idx = blockIdx.x * blockDim.x + threadIdx.x;
    if (idx >= ct.end4[8]) return;
    int ti = 0;
    while (idx >= ct.end4[ti]) ti++;
    int off = ti ? idx - ct.end4[ti - 1] : idx;
    float4 v = ((const float4*)ct.src[ti])[off];
    __half2* d = (__half2*)ct.dst[ti];
    d[off * 2]     = __floats2half2_rn(v.x, v.y);
    d[off * 2 + 1] = __floats2half2_rn(v.z, v.w);
}

// ---------------- shared task structs ----------------
// modes: 0 plain fp32+bias  1 q_nope  2 q_rope  3 k_nope  4 k_rope  5 v_scatter  6 plain half+bias
struct GTask {
    const void* X; const void* W; const float* bias; void* Y;
    int K, mode, ntx, base, ldx, ldw;
};
struct GTasks { GTask t[6]; int n; int nblocks; };

// =============== WIDE GEMM: 128x128 tiles, TBK=64, 3-stage, 2 CTAs/SM ===============
#define GST_W 36
#define STG_W 4608
#define MG_SMEM_W (3 * 2 * STG_W * 4)    // 110592 B

__global__ __launch_bounds__(256, 2)
void gemm_wide(GTasks tasks)
{
    extern __shared__ uint32_t sm4[];
    const uint32_t sb = smem_u32(sm4);

    int bid = blockIdx.x;
    if (bid >= tasks.nblocks) return;
    int ti = 0;
#pragma unroll 1
    while (ti + 1 < tasks.n && bid >= tasks.t[ti + 1].base) ti++;
    const GTask tk = tasks.t[ti];
    int lb = bid - tk.base;
    int tilex = lb % tk.ntx;
    int tiley = lb / tk.ntx;

    const int tid  = threadIdx.x;
    const int lane = tid & 31;
    const int wid  = tid >> 5;
    const int g    = lane >> 2;
    const int t    = lane & 3;
    const int wm   = wid & 3;
    const int wn   = wid >> 2;
    const int K    = tk.K;
    const int ldx  = tk.ldx;
    const int ldw  = tk.ldw;
    const int kiters = K >> 6;

    const int lm = lane >> 3, lr = lane & 7;
    const int constA = ((lm & 1) * 8 + lr) * GST_W + (lm >> 1) * 4;
    const int constB = ((lm >> 1) * 8 + lr) * GST_W + (lm & 1) * 4;

    const __half* Xb = (const __half*)tk.X + (size_t)(tiley * 128) * ldx;
    const __half* Wb = (const __half*)tk.W + (size_t)(tilex * 128) * ldw;

    float acc[2][8][4];
#pragma unroll
    for (int mt = 0; mt < 2; mt++)
#pragma unroll
        for (int nt = 0; nt < 8; nt++)
#pragma unroll
            for (int j = 0; j < 4; j++) acc[mt][nt][j] = 0.f;

#pragma unroll
    for (int st = 0; st < 2; st++) {
        uint32_t As = sb + st * (2 * STG_W) * 4;
        uint32_t Bs = As + STG_W * 4;
        int k0 = st * 64;
#pragma unroll
        for (int i = 0; i < 8; i++) {
            int ch = tid + (i & 3) * 256;
            int r = ch >> 3, c = ch & 7;
            if (i < 4) cpasync16(As + (r * GST_W + c * 4) * 4, Xb + (size_t)r * ldx + k0 + c * 8);
            else       cpasync16(Bs + (r * GST_W + c * 4) * 4, Wb + (size_t)r * ldw + k0 + c * 8);
        }
        asm volatile("cp.async.commit_group;");
    }

    for (int ki = 0; ki < kiters; ki++) {
        if (ki + 1 < kiters) asm volatile("cp.async.wait_group 1;");
        else                 asm volatile("cp.async.wait_group 0;");
        __syncthreads();

        if (ki + 2 < kiters) {
            int st = (ki + 2) % 3;
            uint32_t As = sb + st * (2 * STG_W) * 4;
            uint32_t Bs = As + STG_W * 4;
            int k0 = (ki + 2) * 64;
#pragma unroll
            for (int i = 0; i < 8; i++) {
                int ch = tid + (i & 3) * 256;
                int r = ch >> 3, c = ch & 7;
                if (i < 4) cpasync16(As + (r * GST_W + c * 4) * 4, Xb + (size_t)r * ldx + k0 + c * 8);
                else       cpasync16(Bs + (r * GST_W + c * 4) * 4, Wb + (size_t)r * ldw + k0 + c * 8);
            }
            asm volatile("cp.async.commit_group;");
        }

        const uint32_t As = sb + (ki % 3) * (2 * STG_W) * 4;
        const uint32_t Bs = As + STG_W * 4;

#pragma unroll
        for (int kk = 0; kk < 4; kk++) {
            uint32_t af[2][4];
            ldsm_x4(af[0], As + (constA + (wm * 32)      * GST_W + kk * 8) * 4);
            ldsm_x4(af[1], As + (constA + (wm * 32 + 16) * GST_W + kk * 8) * 4);
#pragma unroll
            for (int ntp = 0; ntp < 4; ntp++) {
                uint32_t bf[4];
                ldsm_x4(bf, Bs + (constB + (wn * 64 + ntp * 16) * GST_W + kk * 8) * 4);
                mma16(acc[0][2 * ntp],     af[0], bf);
                mma16(acc[0][2 * ntp + 1], af[0], bf + 2);
                mma16(acc[1][2 * ntp],     af[1], bf);
                mma16(acc[1][2 * ntp + 1], af[1], bf + 2);
            }
        }
    }

    const int N = tk.ntx << 7;
    const int mode = tk.mode;

#pragma unroll
    for (int mt = 0; mt < 2; mt++) {
        int r0 = tiley * 128 + wm * 32 + mt * 16 + g;
#pragma unroll
        for (int nt = 0; nt < 8; nt++) {
            int n = tilex * 128 + wn * 64 + nt * 8 + 2 * t;
            float b0 = tk.bias[n], b1 = tk.bias[n + 1];
            float x0 = acc[mt][nt][0] + b0, y0 = acc[mt][nt][1] + b1;
            float x1 = acc[mt][nt][2] + b0, y1 = acc[mt][nt][3] + b1;

            if (mode == 0) {
                float* Yf = (float*)tk.Y;
                *(float2*)&Yf[(size_t)r0 * N + n]       = make_float2(x0, y0);
                *(float2*)&Yf[(size_t)(r0 + 8) * N + n] = make_float2(x1, y1);
            } else {   // mode 6
                __half* Yh = (__half*)tk.Y;
                *(__half2*)&Yh[(size_t)r0 * N + n]       = __floats2half2_rn(x0, y0);
                *(__half2*)&Yh[(size_t)(r0 + 8) * N + n] = __floats2half2_rn(x1, y1);
            }
        }
    }
}

// =============== NARROW GEMM: 128x64 tiles, TBK=32, 4-stage, 3 CTAs/SM ===============
#define GST_N 20
#define STG_NA 2560
#define STG_NB 1280
#define STG_N (STG_NA + STG_NB)          // 3840
#define NSTAGE_N 4
#define MG_SMEM_N (NSTAGE_N * STG_N * 4) // 61440 B

__global__ __launch_bounds__(256, 3)
void gemm_narrow(GTasks tasks)
{
    extern __shared__ uint32_t sm4[];
    const uint32_t sb = smem_u32(sm4);

    int bid = blockIdx.x;
    if (bid >= tasks.nblocks) return;
    int ti = 0;
#pragma unroll 1
    while (ti + 1 < tasks.n && bid >= tasks.t[ti + 1].base) ti++;
    const GTask tk = tasks.t[ti];
    int lb = bid - tk.base;
    int tilex = lb % tk.ntx;
    int tiley = lb / tk.ntx;

    const int tid  = threadIdx.x;
    const int lane = tid & 31;
    const int wid  = tid >> 5;
    const int g    = lane >> 2;
    const int t    = lane & 3;
    const int wm   = wid & 3;
    const int wn   = wid >> 2;
    const int K    = tk.K;
    const int ldx  = tk.ldx;
    const int ldw  = tk.ldw;

    const int lm = lane >> 3, lr = lane & 7;
    const int constA = ((lm & 1) * 8 + lr) * GST_N + (lm >> 1) * 4;
    const int constB = ((lm >> 1) * 8 + lr) * GST_N + (lm & 1) * 4;

    const __half* Xb = (const __half*)tk.X + (size_t)(tiley * 128) * ldx;
    const __half* Wb = (const __half*)tk.W + (size_t)(tilex * 64) * ldw;

    float acc[2][4][4];
#pragma unroll
    for (int mt = 0; mt < 2; mt++)
#pragma unroll
        for (int nt = 0; nt < 4; nt++)
#pragma unroll
            for (int j = 0; j < 4; j++) acc[mt][nt][j] = 0.f;

    auto load_chunk = [&](int j) {
        uint32_t Sb = sb + (j % NSTAGE_N) * STG_N * 4;
#pragma unroll
        for (int i = 0; i < 3; i++) {
            int ch = tid + i * 256;
            if (ch < 512) {
                int r = ch >> 2, c = ch & 3;
                cpasync16(Sb + (r * GST_N + c * 4) * 4, Xb + (size_t)r * ldx + j * 32 + c * 8);
            } else {
                int ch2 = ch - 512;
                int r = ch2 >> 2, c = ch2 & 3;
                cpasync16(Sb + (STG_NA + r * GST_N + c * 4) * 4, Wb + (size_t)r * ldw + j * 32 + c * 8);
            }
        }
    };

    auto compute_stage = [&](int st) {
        const uint32_t As = sb + st * STG_N * 4;
        const uint32_t Bs = As + STG_NA * 4;
#pragma unroll
        for (int kk = 0; kk < 2; kk++) {
            uint32_t af[2][4];
            ldsm_x4(af[0], As + (constA + (wm * 32)      * GST_N + kk * 8) * 4);
            ldsm_x4(af[1], As + (constA + (wm * 32 + 16) * GST_N + kk * 8) * 4);
#pragma unroll
            for (int ntp = 0; ntp < 2; ntp++) {
                uint32_t bf[4];
                ldsm_x4(bf, Bs + (constB + (wn * 32 + ntp * 16) * GST_N + kk * 8) * 4);
                mma16(acc[0][2 * ntp],     af[0], bf);
                mma16(acc[0][2 * ntp + 1], af[0], bf + 2);
                mma16(acc[1][2 * ntp],     af[1], bf);
                mma16(acc[1][2 * ntp + 1], af[1], bf + 2);
            }
        }
    };

    if (K == 128) {
        // fast path: all 4 chunks fit in the 4 stages; single wait + barrier
#pragma unroll
        for (int j = 0; j < 4; j++) load_chunk(j);
        asm volatile("cp.async.commit_group;");
        asm volatile("cp.async.wait_group 0;");
        __syncthreads();
#pragma unroll
        for (int ki = 0; ki < 4; ki++) compute_stage(ki);
    } else {
        const int kiters = K >> 5;
#pragma unroll
        for (int j = 0; j < NSTAGE_N - 1; j++) {
            load_chunk(j);
            asm volatile("cp.async.commit_group;");
        }
        for (int ki = 0; ki < kiters; ki++) {
            asm volatile("cp.async.wait_group 2;");
            __syncthreads();
            if (ki + NSTAGE_N - 1 < kiters) load_chunk(ki + NSTAGE_N - 1);
            asm volatile("cp.async.commit_group;");
            compute_stage(ki % NSTAGE_N);
        }
    }

    const float scale = 0.08838834764831845f;   // 1/sqrt(128)
    const int mode = tk.mode;

#pragma unroll
    for (int mt = 0; mt < 2; mt++) {
        int r0 = tiley * 128 + wm * 32 + mt * 16 + g;
#pragma unroll
        for (int nt = 0; nt < 4; nt++) {
            int n = tilex * 64 + wn * 32 + nt * 8 + 2 * t;
            float b0 = tk.bias[n], b1 = tk.bias[n + 1];
            float x0 = acc[mt][nt][0] + b0, y0 = acc[mt][nt][1] + b1;
            float x1 = acc[mt][nt][2] + b0, y1 = acc[mt][nt][3] + b1;

            int s0 = r0 & 2047;
            int f = n;
            if (mode == 2 || mode == 4) {   // rope
                f = 768 + n;
                float fr = g_freq[n >> 1];
                float a0 = (float)s0 * fr;
                float a1 = (float)(s0 + 8) * fr;
                float c0 = cosf(a0), sn0 = sinf(a0);
                float c1 = cosf(a1), sn1 = sinf(a1);
                float tx0 = x0 * c0 - y0 * sn0, ty0 = x0 * sn0 + y0 * c0;
                float tx1 = x1 * c1 - y1 * sn1, ty1 = x1 * sn1 + y1 * c1;
                x0 = tx0; y0 = ty0; x1 = tx1; y1 = ty1;
            }
            if (mode <= 2) { x0 *= scale; y0 *= scale; x1 *= scale; y1 *= scale; }
            int h = f >> 7, d = f & 127;
            int b = r0 >> 11;
            __half* Yh = (__half*)tk.Y;
            size_t d0 = (((size_t)(b * H_ + h)) * S_ + s0) * 128 + d;
            *(__half2*)&Yh[d0]           = __floats2half2_rn(x0, y0);
            *(__half2*)&Yh[d0 + 8 * 128] = __floats2half2_rn(x1, y1);
        }
    }
}

// ---------------- FP16 flash attention (R13, unchanged) ----------------
#define AKST 68
#define OFF_K0  0
#define OFF_K1  4352
#define OFF_VN0 8704
#define OFF_VN1 13056
#define ATT_SMEM_BYTES (17408 * 4)   // 69632

__global__ __launch_bounds__(256, 1)
void attn_f16(const __half* __restrict__ q, const __half* __restrict__ k,
              const __half* __restrict__ v, __half* __restrict__ o)
{
    extern __shared__ uint32_t sm4[];
    const uint32_t sb = smem_u32(sm4);

    const int tid  = threadIdx.x;
    const int lane = tid & 31;
    const int wid  = tid >> 5;
    const int g    = lane >> 2;
    const int t    = lane & 3;
    const int qt   = (S_ / 128 - 1) - blockIdx.x;
    const int bh   = blockIdx.y;
    const int b    = bh / H_, h = bh % H_;
    const size_t base = (size_t)bh * S_ * 128;

    const int lm = lane >> 3, lr = lane & 7;
    const int constA = ((lm & 1) * 8 + lr) * AKST + (lm >> 1) * 4;
    const int constB = ((lm >> 1) * 8 + lr) * AKST + (lm & 1) * 4;

    {
        const __half* qg = q + base + (size_t)qt * 128 * 128;
#pragma unroll
        for (int i = 0; i < 8; i++) {
            int ch = tid + i * 256;
            int r = ch >> 4, c4 = (ch & 15) << 2;
            cpasync16(sb + (r * AKST + c4) * 4, qg + (size_t)r * 128 + ((ch & 15) << 3));
        }
        asm volatile("cp.async.commit_group;");
        asm volatile("cp.async.wait_group 0;");
        __syncthreads();
    }

    const int wr = wid * 16;
    uint32_t qf[8][4];
#pragma unroll
    for (int kk = 0; kk < 8; kk++)
        ldsm_x4(qf[kk], sb + (constA + wr * AKST + kk * 8) * 4);
    __syncthreads();

    float of[16][4];
#pragma unroll
    for (int nt = 0; nt < 16; nt++)
#pragma unroll
        for (int j = 0; j < 4; j++) of[nt][j] = 0.f;
    float m0 = -CUDART_INF_F, m1 = -CUDART_INF_F, l0 = 0.f, l1 = 0.f;

    const int row0g = qt * 128 + wr + g;
    const int row1g = row0g + 8;
    const int nkt = 2 * qt + 2;

    {
        const __half* kg = k + base;
        const __half* vg = v + base;
#pragma unroll
        for (int i = 0; i < 8; i++) {
            int ch = tid + (i & 3) * 256;
            int r = ch >> 4, c4 = (ch & 15) << 2, c8 = (ch & 15) << 3;
            if (i < 4) cpasync16(sb + (OFF_K0  + r * AKST + c4) * 4, kg + (size_t)r * 128 + c8);
            else       cpasync16(sb + (OFF_VN0 + r * AKST + c4) * 4, vg + (size_t)r * 128 + c8);
        }
        asm volatile("cp.async.commit_group;");
    }

    for (int kt = 0; kt < nkt; kt++) {
        asm volatile("cp.async.wait_group 0;");
        __syncthreads();

        if (kt + 1 < nkt) {
            const __half* kg = k + base + (size_t)(kt + 1) * 64 * 128;
            const __half* vg = v + base + (size_t)(kt + 1) * 64 * 128;
            uint32_t Kd = sb + ((((kt + 1) & 1) ? OFF_K1  : OFF_K0))  * 4;
            uint32_t Vd = sb + ((((kt + 1) & 1) ? OFF_VN1 : OFF_VN0)) * 4;
#pragma unroll
            for (int i = 0; i < 8; i++) {
                int ch = tid + (i & 3) * 256;
                int r = ch >> 4, c4 = (ch & 15) << 2, c8 = (ch & 15) << 3;
                if (i < 4) cpasync16(Kd + (r * AKST + c4) * 4, kg + (size_t)r * 128 + c8);
                else       cpasync16(Vd + (r * AKST + c4) * 4, vg + (size_t)r * 128 + c8);
            }
            asm volatile("cp.async.commit_group;");
        }

        const uint32_t Kb = sb + (((kt & 1) ? OFF_K1  : OFF_K0))  * 4;
        const uint32_t Vn = sb + (((kt & 1) ? OFF_VN1 : OFF_VN0)) * 4;

        float sc[8][4];
#pragma unroll
        for (int nt = 0; nt < 8; nt++)
#pragma unroll
            for (int j = 0; j < 4; j++) sc[nt][j] = 0.f;

#pragma unroll
        for (int kk = 0; kk < 8; kk++) {
#pragma unroll
            for (int ntp = 0; ntp < 4; ntp++) {
                uint32_t bf[4];
                ldsm_x4(bf, Kb + (constB + ntp * 16 * AKST + kk * 8) * 4);
                mma16(sc[2 * ntp],     qf[kk], bf);
                mma16(sc[2 * ntp + 1], qf[kk], bf + 2);
            }
        }

        if (kt >= 2 * qt) {
            int cbase = kt * 64 + 2 * t;
#pragma unroll
            for (int nt = 0; nt < 8; nt++) {
                int col = cbase + nt * 8;
                if (col     > row0g) sc[nt][0] = -CUDART_INF_F;
                if (col + 1 > row0g) sc[nt][1] = -CUDART_INF_F;
                if (col     > row1g) sc[nt][2] = -CUDART_INF_F;
                if (col + 1 > row1g) sc[nt][3] = -CUDART_INF_F;
            }
        }

        float rmax0 = -CUDART_INF_F, rmax1 = -CUDART_INF_F;
#pragma unroll
        for (int nt = 0; nt < 8; nt++) {
            rmax0 = fmaxf(rmax0, fmaxf(sc[nt][0], sc[nt][1]));
            rmax1 = fmaxf(rmax1, fmaxf(sc[nt][2], sc[nt][3]));
        }
        rmax0 = fmaxf(rmax0, __shfl_xor_sync(0xffffffffu, rmax0, 1, 4));
        rmax0 = fmaxf(rmax0, __shfl_xor_sync(0xffffffffu, rmax0, 2, 4));
        rmax1 = fmaxf(rmax1, __shfl_xor_sync(0xffffffffu, rmax1, 1, 4));
        rmax1 = fmaxf(rmax1, __shfl_xor_sync(0xffffffffu, rmax1, 2, 4));

        float mn0 = fmaxf(m0, rmax0);
        float mn1 = fmaxf(m1, rmax1);
        float fac0 = __expf(m0 - mn0);
        float fac1 = __expf(m1 - mn1);
        m0 = mn0; m1 = mn1;

        float rs0 = 0.f, rs1 = 0.f;
#pragma unroll
        for (int nt = 0; nt < 8; nt++) {
            float p0 = __expf(sc[nt][0] - mn0);
            float p1 = __expf(sc[nt][1] - mn0);
            float p2 = __expf(sc[nt][2] - mn1);
            float p3 = __expf(sc[nt][3] - mn1);
            sc[nt][0] = p0; sc[nt][1] = p1; sc[nt][2] = p2; sc[nt][3] = p3;
            rs0 += p0 + p1; rs1 += p2 + p3;
        }
        rs0 += __shfl_xor_sync(0xffffffffu, rs0, 1, 4);
        rs0 += __shfl_xor_sync(0xffffffffu, rs0, 2, 4);
        rs1 += __shfl_xor_sync(0xffffffffu, rs1, 1, 4);
        rs1 += __shfl_xor_sync(0xffffffffu, rs1, 2, 4);
        l0 = l0 * fac0 + rs0;
        l1 = l1 * fac1 + rs1;

#pragma unroll
        for (int nt = 0; nt < 16; nt++) {
            of[nt][0] *= fac0; of[nt][1] *= fac0;
            of[nt][2] *= fac1; of[nt][3] *= fac1;
        }

#pragma unroll
        for (int kk = 0; kk < 4; kk++) {
            uint32_t ap[4];
            ap[0] = packh2(sc[2 * kk][0],     sc[2 * kk][1]);
            ap[1] = packh2(sc[2 * kk][2],     sc[2 * kk][3]);
            ap[2] = packh2(sc[2 * kk + 1][0], sc[2 * kk + 1][1]);
            ap[3] = packh2(sc[2 * kk + 1][2], sc[2 * kk + 1][3]);
#pragma unroll
            for (int ntp = 0; ntp < 8; ntp++) {
                uint32_t bf[4];
                ldsm_x4t(bf, Vn + (constA + kk * 16 * AKST + ntp * 8) * 4);
                mma16(of[2 * ntp],     ap, bf);
                mma16(of[2 * ntp + 1], ap, bf + 2);
            }
        }
    }

    float inv0 = 1.0f / l0;
    float inv1 = 1.0f / l1;
    size_t orow0 = ((size_t)(b * S_ + row0g)) * 1536 + h * 128;
    size_t orow1 = ((size_t)(b * S_ + row1g)) * 1536 + h * 128;
#pragma unroll
    for (int nt = 0; nt < 16; nt++) {
        int col = nt * 8 + 2 * t;
        *(__half2*)&o[orow0 + col] = __floats2half2_rn(of[nt][0] * inv0, of[nt][1] * inv0);
        *(__half2*)&o[orow1 + col] = __floats2half2_rn(of[nt][2] * inv1, of[nt][3] * inv1);
    }
}

// ---------------- launch ----------------
extern "C" void kernel_launch(void* const* d_in, const int* in_sizes, int n_in,
                              void* d_out, int out_size)
{
    const float* x         = (const float*)d_in[0];
    const float* W_dkv     = (const float*)d_in[2];
    const float* b_dkv     = (const float*)d_in[3];
    const float* W_dq      = (const float*)d_in[4];
    const float* b_dq      = (const float*)d_in[5];
    const float* W_uk_nope = (const float*)d_in[6];
    const float* b_uk_nope = (const float*)d_in[7];
    const float* W_uv      = (const float*)d_in[8];
    const float* b_uv      = (const float*)d_in[9];
    const float* W_uq_nope = (const float*)d_in[10];
    const float* b_uq_nope = (const float*)d_in[11];
    const float* W_uq_rope = (const float*)d_in[12];
    const float* b_uq_rope = (const float*)d_in[13];
    const float* W_uk_rope = (const float*)d_in[14];
    const float* b_uk_rope = (const float*)d_in[15];
    const float* W_o       = (const float*)d_in[16];
    const float* b_o       = (const float*)d_in[17];
    float* out = (float*)d_out;

    __half *Cq, *Ckv, *q, *k, *vh, *o, *xh, *Wh;
    cudaGetSymbolAddress((void**)&Cq,  g_Cq);
    cudaGetSymbolAddress((void**)&Ckv, g_Ckv);
    cudaGetSymbolAddress((void**)&q,   g_q);
    cudaGetSymbolAddress((void**)&k,   g_k);
    cudaGetSymbolAddress((void**)&vh,  g_vh);
    cudaGetSymbolAddress((void**)&o,   g_o);
    cudaGetSymbolAddress((void**)&xh,  g_xh);
    cudaGetSymbolAddress((void**)&Wh,  g_Wh);

    cudaFuncSetAttribute(attn_f16, cudaFuncAttributeMaxDynamicSharedMemorySize, ATT_SMEM_BYTES);
    cudaFuncSetAttribute(gemm_wide, cudaFuncAttributeMaxDynamicSharedMemorySize, MG_SMEM_W);
    cudaFuncSetAttribute(gemm_narrow, cudaFuncAttributeMaxDynamicSharedMemorySize, MG_SMEM_N);

    dim3 t(256);
    init_freq_kernel<<<2, 192>>>();

    // convert x and all fp16-consumed weights
    CTasks ct;
    ct.src[0] = x;         ct.dst[0] = xh;
    ct.src[1] = W_uq_nope; ct.dst[1] = Wh + WR_UQN;
    ct.src[2] = W_uq_rope; ct.dst[2] = Wh + WR_UQR;
    ct.src[3] = W_uk_nope; ct.dst[3] = Wh + WR_UKN;
    ct.src[4] = W_uv;      ct.dst[4] = Wh + WR_UV;
    ct.src[5] = W_uk_rope; ct.dst[5] = Wh + WR_UKR;
    ct.src[6] = W_o;       ct.dst[6] = Wh + WR_O;
    ct.src[7] = W_dq;      ct.dst[7] = Wh + WR_DQ;
    ct.src[8] = W_dkv;     ct.dst[8] = Wh + WR_DKV;
    int counts[9] = {MROWS*768, 98304, 98304, 98304, 196608, 589824, 1179648, 98304, 98304};
    int acc4 = 0;
    for (int i = 0; i < 9; i++) { acc4 += counts[i] / 4; ct.end4[i] = acc4; }
    conv_half_kernel<<<(acc4 + 255) / 256, 256>>>(ct);

    // latent projections (wide GEMM, half outputs)
    GTasks gl;
    gl.n = 2;
    gl.nblocks = 128;
    gl.t[0] = { xh, Wh + WR_DQ,  b_dq,  Cq,  768, 6, 1, 0,  768, 768 };
    gl.t[1] = { xh, Wh + WR_DKV, b_dkv, Ckv, 768, 6, 1, 64, 768, 768 };
    gemm_wide<<<128, t, MG_SMEM_W>>>(gl);

    // five up-projections fused (narrow GEMM, heavy-K k_rope first)
    GTasks gt;
    gt.n = 5;
    gt.nblocks = 4608;
    gt.t[0] = { xh,  Wh + WR_UKR, b_uk_rope, k,   768, 4, 12, 0,    768, 768 };
    gt.t[1] = { Ckv, Wh + WR_UV,  b_uv,      vh,  128, 5, 24, 768,  128, 128 };
    gt.t[2] = { Cq,  Wh + WR_UQN, b_uq_nope, q,   128, 1, 12, 2304, 128, 128 };
    gt.t[3] = { Cq,  Wh + WR_UQR, b_uq_rope, q,   128, 2, 12, 3072, 128, 128 };
    gt.t[4] = { Ckv, Wh + WR_UKN, b_uk_nope, k,   128, 3, 12, 3840, 128, 128 };
    gemm_narrow<<<4608, t, MG_SMEM_N>>>(gt);

    // fp16 flash attention
    attn_f16<<<dim3(S_ / 128, B_ * H_), t, ATT_SMEM_BYTES>>>(q, k, vh, o);

    // output projection (single wide GEMM launch, fp32 + bias)
    GTasks go;
    go.n = 1;
    go.nblocks = 384;
    go.t[0] = { o, Wh + WR_O, b_o, out, 1536, 0, 6, 0, 1536, 1536 };
    gemm_wide<<<384, t, MG_SMEM_W>>>(go);
}